// round 6
// baseline (speedup 1.0000x reference)
#include <cuda_runtime.h>
#include <cuda_bf16.h>

// Problem constants (fixed by the reference setup_inputs)
#define DIM_K 512
#define MAX_N 16384
#define MAX_M 4096

// Scratch for row norms (no cudaMalloc allowed)
__device__ float g_xsq[MAX_N];
__device__ float g_csq[MAX_M];

// ---------------------------------------------------------------------------
// Row-norm kernels: one block of 128 threads per row, each thread one float4.
// ---------------------------------------------------------------------------
__global__ void xnorm_kernel(const float* __restrict__ x) {
    int row = blockIdx.x;
    const float4* p = reinterpret_cast<const float4*>(x + (size_t)row * DIM_K);
    float4 v = p[threadIdx.x];                 // 128 threads * 4 = 512 elems
    float s = v.x * v.x + v.y * v.y + v.z * v.z + v.w * v.w;
    // warp reduce
    #pragma unroll
    for (int off = 16; off > 0; off >>= 1)
        s += __shfl_down_sync(0xffffffffu, s, off);
    __shared__ float ws[4];
    int wid = threadIdx.x >> 5;
    int lid = threadIdx.x & 31;
    if (lid == 0) ws[wid] = s;
    __syncthreads();
    if (threadIdx.x == 0)
        g_xsq[row] = ws[0] + ws[1] + ws[2] + ws[3];
}

__global__ void cnorm_kernel(const float* __restrict__ c) {
    int row = blockIdx.x;
    const float4* p = reinterpret_cast<const float4*>(c + (size_t)row * DIM_K);
    float4 v = p[threadIdx.x];
    float s = v.x * v.x + v.y * v.y + v.z * v.z + v.w * v.w;
    #pragma unroll
    for (int off = 16; off > 0; off >>= 1)
        s += __shfl_down_sync(0xffffffffu, s, off);
    __shared__ float ws[4];
    int wid = threadIdx.x >> 5;
    int lid = threadIdx.x & 31;
    if (lid == 0) ws[wid] = s;
    __syncthreads();
    if (threadIdx.x == 0)
        g_csq[row] = ws[0] + ws[1] + ws[2] + ws[3];
}

// ---------------------------------------------------------------------------
// Main distance kernel: 128x128 block tile, 8x8 per thread, K-tile 16.
// C[n][m] = xsq[n] + csq[m] - 2 * dot(A[n,:], B[m,:])
// A: [N, 512] row-major, B: [M, 512] row-major (NT GEMM).
// ---------------------------------------------------------------------------
#define BK 16
#define BT 128   // block tile (both dims)
#define TM 8
#define TN 8

__global__ __launch_bounds__(256, 2)
void dist_kernel(const float* __restrict__ A, const float* __restrict__ B,
                 float* __restrict__ C, int N, int M) {
    __shared__ float As[BK][BT];   // [k][row]
    __shared__ float Bs[BK][BT];   // [k][col]

    const int tid = threadIdx.x;
    const int tx = tid & 15;       // 0..15  -> col group
    const int ty = tid >> 4;       // 0..15  -> row group
    const int rowBase = blockIdx.y * BT;
    const int colBase = blockIdx.x * BT;

    float acc[TM][TN];
    #pragma unroll
    for (int i = 0; i < TM; i++)
        #pragma unroll
        for (int j = 0; j < TN; j++)
            acc[i][j] = 0.0f;

    for (int k0 = 0; k0 < DIM_K; k0 += BK) {
        // Load A tile: 128 rows x 16 k = 512 float4 loads, 2 per thread.
        #pragma unroll
        for (int i = 0; i < 2; i++) {
            int idx = tid + i * 256;        // 0..511
            int r   = idx >> 2;             // 0..127
            int kq  = (idx & 3) << 2;       // 0,4,8,12
            float4 v = *reinterpret_cast<const float4*>(
                A + (size_t)(rowBase + r) * DIM_K + k0 + kq);
            As[kq + 0][r] = v.x;
            As[kq + 1][r] = v.y;
            As[kq + 2][r] = v.z;
            As[kq + 3][r] = v.w;
        }
        // Load B tile (same pattern)
        #pragma unroll
        for (int i = 0; i < 2; i++) {
            int idx = tid + i * 256;
            int r   = idx >> 2;
            int kq  = (idx & 3) << 2;
            float4 v = *reinterpret_cast<const float4*>(
                B + (size_t)(colBase + r) * DIM_K + k0 + kq);
            Bs[kq + 0][r] = v.x;
            Bs[kq + 1][r] = v.y;
            Bs[kq + 2][r] = v.z;
            Bs[kq + 3][r] = v.w;
        }
        __syncthreads();

        #pragma unroll
        for (int kk = 0; kk < BK; kk++) {
            float a[TM], b[TN];
            *reinterpret_cast<float4*>(&a[0]) =
                *reinterpret_cast<const float4*>(&As[kk][ty * TM + 0]);
            *reinterpret_cast<float4*>(&a[4]) =
                *reinterpret_cast<const float4*>(&As[kk][ty * TM + 4]);
            *reinterpret_cast<float4*>(&b[0]) =
                *reinterpret_cast<const float4*>(&Bs[kk][tx * TN + 0]);
            *reinterpret_cast<float4*>(&b[4]) =
                *reinterpret_cast<const float4*>(&Bs[kk][tx * TN + 4]);
            #pragma unroll
            for (int i = 0; i < TM; i++)
                #pragma unroll
                for (int j = 0; j < TN; j++)
                    acc[i][j] = fmaf(a[i], b[j], acc[i][j]);
        }
        __syncthreads();
    }

    // Epilogue: dist = xsq + csq - 2*dot
    #pragma unroll
    for (int i = 0; i < TM; i++) {
        int n = rowBase + ty * TM + i;
        float xs = g_xsq[n];
        #pragma unroll
        for (int j = 0; j < TN; j += 4) {
            int m = colBase + tx * TN + j;
            float4 cs = *reinterpret_cast<const float4*>(&g_csq[m]);
            float4 o;
            o.x = xs + cs.x - 2.0f * acc[i][j + 0];
            o.y = xs + cs.y - 2.0f * acc[i][j + 1];
            o.z = xs + cs.z - 2.0f * acc[i][j + 2];
            o.w = xs + cs.w - 2.0f * acc[i][j + 3];
            *reinterpret_cast<float4*>(C + (size_t)n * M + m) = o;
        }
    }
}

// ---------------------------------------------------------------------------
extern "C" void kernel_launch(void* const* d_in, const int* in_sizes, int n_in,
                              void* d_out, int out_size) {
    const float* A = (const float*)d_in[0];   // input  [N, 512]
    const float* B = (const float*)d_in[1];   // centres [M, 512]
    float* C = (float*)d_out;                 // [N, M]

    int N = in_sizes[0] / DIM_K;              // 16384
    int M = in_sizes[1] / DIM_K;              // 4096

    xnorm_kernel<<<N, 128>>>(A);
    cnorm_kernel<<<M, 128>>>(B);

    dim3 grid(M / BT, N / BT);                // (32, 128)
    dist_kernel<<<grid, 256>>>(A, B, C, N, M);
}

// round 8
// speedup vs baseline: 5.6986x; 5.6986x over previous
#include <cuda_runtime.h>
#include <cuda_fp16.h>
#include <cstdint>

#define DIM_K 512
#define NROWS 16384
#define MROWS 4096

// Scratch (no cudaMalloc allowed)
__device__ float g_xsq[NROWS];
__device__ float g_csq[MROWS];
__device__ __half g_Ah[(size_t)NROWS * DIM_K];
__device__ __half g_Bh[(size_t)MROWS * DIM_K];

// ---------------------------------------------------------------------------
// Fused convert(fp32->fp16) + row-norm kernels. Norms stay fp32.
// ---------------------------------------------------------------------------
__global__ void convA_kernel(const float* __restrict__ x) {
    int row = blockIdx.x, tid = threadIdx.x;
    const float4* p = reinterpret_cast<const float4*>(x + (size_t)row * DIM_K);
    float4 v = p[tid];
    __half2* dst = reinterpret_cast<__half2*>(g_Ah + (size_t)row * DIM_K);
    dst[tid * 2 + 0] = __floats2half2_rn(v.x, v.y);
    dst[tid * 2 + 1] = __floats2half2_rn(v.z, v.w);
    float s = v.x * v.x + v.y * v.y + v.z * v.z + v.w * v.w;
    #pragma unroll
    for (int off = 16; off > 0; off >>= 1)
        s += __shfl_down_sync(0xffffffffu, s, off);
    __shared__ float ws[4];
    if ((tid & 31) == 0) ws[tid >> 5] = s;
    __syncthreads();
    if (tid == 0) g_xsq[row] = ws[0] + ws[1] + ws[2] + ws[3];
}

__global__ void convB_kernel(const float* __restrict__ c) {
    int row = blockIdx.x, tid = threadIdx.x;
    const float4* p = reinterpret_cast<const float4*>(c + (size_t)row * DIM_K);
    float4 v = p[tid];
    __half2* dst = reinterpret_cast<__half2*>(g_Bh + (size_t)row * DIM_K);
    dst[tid * 2 + 0] = __floats2half2_rn(v.x, v.y);
    dst[tid * 2 + 1] = __floats2half2_rn(v.z, v.w);
    float s = v.x * v.x + v.y * v.y + v.z * v.z + v.w * v.w;
    #pragma unroll
    for (int off = 16; off > 0; off >>= 1)
        s += __shfl_down_sync(0xffffffffu, s, off);
    __shared__ float ws[4];
    if ((tid & 31) == 0) ws[tid >> 5] = s;
    __syncthreads();
    if (tid == 0) g_csq[row] = ws[0] + ws[1] + ws[2] + ws[3];
}

// ---------------------------------------------------------------------------
// Legacy tensor-core helpers (base-target PTX: ldmatrix + mma.sync + cp.async)
// ---------------------------------------------------------------------------
__device__ __forceinline__ uint32_t smem_u32(const void* p) {
    uint32_t a;
    asm("{ .reg .u64 t; cvta.to.shared.u64 t, %1; cvt.u32.u64 %0, t; }"
        : "=r"(a) : "l"(p));
    return a;
}

__device__ __forceinline__ void cp_async16(uint32_t dst, const void* src) {
    asm volatile("cp.async.cg.shared.global [%0], [%1], 16;"
                 :: "r"(dst), "l"(src) : "memory");
}

__device__ __forceinline__ void ldsm_x4(uint32_t* r, uint32_t addr) {
    asm volatile("ldmatrix.sync.aligned.m8n8.x4.shared.b16 {%0,%1,%2,%3}, [%4];"
                 : "=r"(r[0]), "=r"(r[1]), "=r"(r[2]), "=r"(r[3]) : "r"(addr));
}

__device__ __forceinline__ void mma16816(float* d, const uint32_t* a,
                                         const uint32_t b0, const uint32_t b1) {
    asm volatile(
        "mma.sync.aligned.m16n8k16.row.col.f32.f16.f16.f32 "
        "{%0,%1,%2,%3}, {%4,%5,%6,%7}, {%8,%9}, {%0,%1,%2,%3};"
        : "+f"(d[0]), "+f"(d[1]), "+f"(d[2]), "+f"(d[3])
        : "r"(a[0]), "r"(a[1]), "r"(a[2]), "r"(a[3]), "r"(b0), "r"(b1));
}

// SW128 on 128B rows, relative offsets: r*128 + (cb ^ ((r&7)<<4))
__device__ __forceinline__ uint32_t swz(int r, int cb) {
    return (uint32_t)(r * 128 + (cb ^ ((r & 7) << 4)));
}

// ---------------------------------------------------------------------------
// GEMM: CTA 128x256, BK=64 halves, 4 stages, 8 warps (warp tile 64x64).
// out[n][m] = xsq[n] + csq[m] - 2 * dot(A[n,:], B[m,:])
// ---------------------------------------------------------------------------
#define BM 128
#define BN 256
#define BK 64                       // halves -> 128 B per smem row
#define NS (DIM_K / BK)             // 8
#define STAGES 4
#define A_BYTES (BM * 128)          // 16 KB
#define B_BYTES (BN * 128)          // 32 KB
#define STAGE_BYTES (A_BYTES + B_BYTES)
#define DYN_SMEM (STAGES * STAGE_BYTES + 1024)

__global__ __launch_bounds__(256, 1)
void dist_hmma_kernel(float* __restrict__ C, int M) {
    extern __shared__ char dyn[];
    uint32_t base = (smem_u32(dyn) + 1023u) & ~1023u;

    const int tid  = threadIdx.x;
    const int wid  = tid >> 5;
    const int lane = tid & 31;
    const int rowBase = blockIdx.y * BM;
    const int colBase = blockIdx.x * BN;
    const int wm = (wid & 1) * 64;        // warp row offset in tile
    const int wn = (wid >> 1) * 64;       // warp col offset in tile

    const __half* gA = g_Ah + (size_t)rowBase * DIM_K;
    const __half* gB = g_Bh + (size_t)colBase * DIM_K;

    float acc[4][8][4];
    #pragma unroll
    for (int i = 0; i < 4; i++)
        #pragma unroll
        for (int j = 0; j < 8; j++)
            #pragma unroll
            for (int q = 0; q < 4; q++) acc[i][j][q] = 0.0f;

    // ---- loader: 256 threads, A: 4 chunks, B: 8 chunks (16B each) ----
    auto load_stage = [&](int ks) {
        const int s = ks & (STAGES - 1);
        const uint32_t sA = base + s * STAGE_BYTES;
        const uint32_t sB = sA + A_BYTES;
        const __half* srcA = gA + ks * BK;
        const __half* srcB = gB + ks * BK;
        #pragma unroll
        for (int i = 0; i < 4; i++) {
            int idx = tid + i * 256;            // 0..1023
            int r = idx >> 3, q = idx & 7;
            cp_async16(sA + swz(r, q * 16), srcA + (size_t)r * DIM_K + q * 8);
        }
        #pragma unroll
        for (int i = 0; i < 8; i++) {
            int idx = tid + i * 256;            // 0..2047
            int r = idx >> 3, q = idx & 7;
            cp_async16(sB + swz(r, q * 16), srcB + (size_t)r * DIM_K + q * 8);
        }
    };

    #pragma unroll
    for (int s = 0; s < STAGES - 1; s++) {
        load_stage(s);
        asm volatile("cp.async.commit_group;" ::: "memory");
    }

    // per-lane fragment row/col components
    const int fr = (lane & 7) + ((lane >> 3) & 1) * 8;   // row within 16-tile
    const int fc = (lane >> 4) * 16;                     // byte col offset (k8 half)

    for (int ks = 0; ks < NS; ks++) {
        if (ks + STAGES - 1 < NS) load_stage(ks + STAGES - 1);
        asm volatile("cp.async.commit_group;" ::: "memory");
        asm volatile("cp.async.wait_group %0;" :: "n"(STAGES - 1) : "memory");
        __syncthreads();

        const int s = ks & (STAGES - 1);
        const uint32_t sA = base + s * STAGE_BYTES;
        const uint32_t sB = sA + A_BYTES;

        #pragma unroll
        for (int kk = 0; kk < 4; kk++) {      // 4 x k16 per BK=64
            const int cb = kk * 32 + fc;      // byte col in 128B row
            uint32_t aF[4][4], bR[4][4];
            #pragma unroll
            for (int mi = 0; mi < 4; mi++) {
                int r = wm + mi * 16 + fr;
                ldsm_x4(aF[mi], sA + swz(r, cb));
            }
            #pragma unroll
            for (int j = 0; j < 4; j++) {
                int r = wn + j * 16 + fr;
                ldsm_x4(bR[j], sB + swz(r, cb));
            }
            #pragma unroll
            for (int mi = 0; mi < 4; mi++) {
                #pragma unroll
                for (int j = 0; j < 4; j++) {
                    mma16816(acc[mi][2 * j + 0], aF[mi], bR[j][0], bR[j][2]);
                    mma16816(acc[mi][2 * j + 1], aF[mi], bR[j][1], bR[j][3]);
                }
            }
        }
        __syncthreads();
    }

    // ---- epilogue: out = xsq + csq - 2*dot, float2 stores ----
    #pragma unroll
    for (int mi = 0; mi < 4; mi++) {
        const int row0 = rowBase + wm + mi * 16 + (lane >> 2);
        const float xs0 = g_xsq[row0];
        const float xs1 = g_xsq[row0 + 8];
        #pragma unroll
        for (int nj = 0; nj < 8; nj++) {
            const int col0 = colBase + wn + nj * 8 + (lane & 3) * 2;
            const float2 cs = *reinterpret_cast<const float2*>(&g_csq[col0]);
            float2 o0, o1;
            o0.x = xs0 + cs.x - 2.0f * acc[mi][nj][0];
            o0.y = xs0 + cs.y - 2.0f * acc[mi][nj][1];
            o1.x = xs1 + cs.x - 2.0f * acc[mi][nj][2];
            o1.y = xs1 + cs.y - 2.0f * acc[mi][nj][3];
            *reinterpret_cast<float2*>(C + (size_t)row0 * M + col0) = o0;
            *reinterpret_cast<float2*>(C + (size_t)(row0 + 8) * M + col0) = o1;
        }
    }
}

// ---------------------------------------------------------------------------
extern "C" void kernel_launch(void* const* d_in, const int* in_sizes, int n_in,
                              void* d_out, int out_size) {
    const float* A = (const float*)d_in[0];   // input   [N, 512]
    const float* B = (const float*)d_in[1];   // centres [M, 512]
    float* C = (float*)d_out;                 // [N, M]

    int N = in_sizes[0] / DIM_K;              // 16384
    int M = in_sizes[1] / DIM_K;              // 4096

    cudaFuncSetAttribute(dist_hmma_kernel,
                         cudaFuncAttributeMaxDynamicSharedMemorySize, DYN_SMEM);

    convA_kernel<<<N, 128>>>(A);
    convB_kernel<<<M, 128>>>(B);

    dim3 grid(M / BN, N / BM);                // (16, 128)
    dist_hmma_kernel<<<grid, 256, DYN_SMEM>>>(C, M);
}